// round 1
// baseline (speedup 1.0000x reference)
#include <cuda_runtime.h>
#include <cuda_bf16.h>
#include <math.h>

#define BATCH 2
#define SEQ   2048
#define DIN   2048
#define NHEAD 16
#define HDIM  128
#define HPAIR (HDIM/2)          // 64 rope pairs per head
#define MROWS (BATCH*SEQ)       // 4096
#define QKVN  (3*DIN)           // 6144

// ---------------- scratch (device globals; no allocs allowed) ----------------
__device__ float g_qkv[(size_t)MROWS * QKVN];   // 96 MB
__device__ float g_att[(size_t)MROWS * DIN];    // 32 MB
__device__ float g_cos[SEQ * HPAIR];
__device__ float g_sin[SEQ * HPAIR];

// ---------------- rope freq table ----------------
__global__ void freq_kernel() {
    int t = blockIdx.x * blockDim.x + threadIdx.x;
    if (t >= SEQ * HPAIR) return;
    int s = t >> 6;          // seq pos
    int p = t & 63;          // pair index
    float inv = (float)(1.0 / pow(10000.0, (double)(2 * p) / (double)HDIM));
    float ang = (float)s * inv;
    float sn, cs;
    sincosf(ang, &sn, &cs);
    g_cos[t] = cs;
    g_sin[t] = sn;
}

// ---------------- rope applied to q and k in qkv buffer ----------------
__global__ void rope_kernel(float* __restrict__ qkv) {
    int t = blockIdx.x * blockDim.x + threadIdx.x;
    if (t >= BATCH * SEQ * NHEAD * HPAIR) return;
    int p = t & 63;
    int h = (t >> 6) & (NHEAD - 1);
    int s = (t >> 10) & (SEQ - 1);
    int b = t >> 21;
    int row = b * SEQ + s;
    float c  = g_cos[s * HPAIR + p];
    float sn = g_sin[s * HPAIR + p];
    size_t base = (size_t)row * QKVN + h * HDIM + 2 * p;
    // q
    float q1 = qkv[base], q2 = qkv[base + 1];
    qkv[base]     = q1 * c - q2 * sn;
    qkv[base + 1] = q1 * sn + q2 * c;
    // k
    size_t kb = base + DIN;
    float k1 = qkv[kb], k2 = qkv[kb + 1];
    qkv[kb]     = k1 * c - k2 * sn;
    qkv[kb + 1] = k1 * sn + k2 * c;
}

// ---------------- fp32 tiled GEMM: C[M,N] = A[M,K] * B[K,N], row-major ----------------
// 128x128 tile, BK=16, 256 threads, 8x8 per-thread micro-tile.
__global__ __launch_bounds__(256) void sgemm128(
    const float* __restrict__ A, const float* __restrict__ B,
    float* __restrict__ C, int M, int N, int K)
{
    __shared__ float As[16][128];
    __shared__ float Bs[16][128];

    int t  = threadIdx.x;
    int tx = t & 15;          // n direction
    int ty = t >> 4;          // m direction
    int tn0 = tx * 8;
    int tm0 = ty * 8;

    const float* Ab = A + (size_t)blockIdx.y * 128 * K;
    const float* Bb = B + (size_t)blockIdx.x * 128;

    float acc[8][8];
    #pragma unroll
    for (int i = 0; i < 8; ++i)
        #pragma unroll
        for (int j = 0; j < 8; ++j) acc[i][j] = 0.f;

    for (int k0 = 0; k0 < K; k0 += 16) {
        // A tile: 128 rows x 16 cols -> store transposed As[k][m]
        #pragma unroll
        for (int i = 0; i < 2; ++i) {
            int f   = t * 2 + i;          // 0..511 float4s
            int row = f >> 2;
            int c4  = f & 3;
            float4 v = *(const float4*)(Ab + (size_t)row * K + k0 + c4 * 4);
            As[c4 * 4 + 0][row] = v.x;
            As[c4 * 4 + 1][row] = v.y;
            As[c4 * 4 + 2][row] = v.z;
            As[c4 * 4 + 3][row] = v.w;
        }
        // B tile: 16 rows x 128 cols -> direct
        #pragma unroll
        for (int i = 0; i < 2; ++i) {
            int f   = t * 2 + i;
            int row = f >> 5;
            int c4  = f & 31;
            *(float4*)(&Bs[row][c4 * 4]) =
                *(const float4*)(Bb + (size_t)(k0 + row) * N + c4 * 4);
        }
        __syncthreads();

        #pragma unroll
        for (int k = 0; k < 16; ++k) {
            float a[8], b[8];
            *(float4*)(a)     = *(float4*)(&As[k][tm0]);
            *(float4*)(a + 4) = *(float4*)(&As[k][tm0 + 4]);
            *(float4*)(b)     = *(float4*)(&Bs[k][tn0]);
            *(float4*)(b + 4) = *(float4*)(&Bs[k][tn0 + 4]);
            #pragma unroll
            for (int i = 0; i < 8; ++i)
                #pragma unroll
                for (int j = 0; j < 8; ++j)
                    acc[i][j] = fmaf(a[i], b[j], acc[i][j]);
        }
        __syncthreads();
    }

    float* Cb = C + (size_t)(blockIdx.y * 128 + tm0) * N + blockIdx.x * 128 + tn0;
    #pragma unroll
    for (int i = 0; i < 8; ++i) {
        *(float4*)(Cb + (size_t)i * N)     = make_float4(acc[i][0], acc[i][1], acc[i][2], acc[i][3]);
        *(float4*)(Cb + (size_t)i * N + 4) = make_float4(acc[i][4], acc[i][5], acc[i][6], acc[i][7]);
    }
}

// ---------------- causal flash attention, fp32 ----------------
// grid: (SEQ/64, NHEAD, BATCH), 256 threads (16x16).
// Q tile 64x128, K tile 64x128, online softmax, O accum in registers.
// smem: Qs[128][64] Ks[128][64] Vs[64][128] Ps[64][68]
__global__ __launch_bounds__(256) void attn_kernel(
    const float* __restrict__ qkv, float* __restrict__ out)
{
    extern __shared__ float smem[];
    float* Qs = smem;                 // [d][q]  128*64
    float* Ks = Qs + 128 * 64;        // [d][k]  128*64
    float* Vs = Ks + 128 * 64;        // [k][d]  64*128
    float* Ps = Vs + 64 * 128;        // [k][q]  64*68 (padded)

    const int qt = blockIdx.x;
    const int h  = blockIdx.y;
    const int b  = blockIdx.z;
    const int t  = threadIdx.x;
    const int tx = t & 15;            // k (for S) / d-group (for O)
    const int ty = t >> 4;            // q

    const float* base = qkv + (size_t)b * SEQ * QKVN + h * HDIM;

    // load Q tile transposed: Qs[d][q]
    for (int i = t; i < 64 * 32; i += 256) {        // 2048 float4
        int r  = i >> 5;                            // q row 0..63
        int c4 = i & 31;                            // d float4 0..31
        float4 v = *(const float4*)(base + (size_t)(qt * 64 + r) * QKVN + c4 * 4);
        Qs[(c4 * 4 + 0) * 64 + r] = v.x;
        Qs[(c4 * 4 + 1) * 64 + r] = v.y;
        Qs[(c4 * 4 + 2) * 64 + r] = v.z;
        Qs[(c4 * 4 + 3) * 64 + r] = v.w;
    }

    float o[4][8];
    float m[4], l[4];
    #pragma unroll
    for (int qi = 0; qi < 4; ++qi) {
        m[qi] = -INFINITY; l[qi] = 0.f;
        #pragma unroll
        for (int dj = 0; dj < 8; ++dj) o[qi][dj] = 0.f;
    }

    const float scale = 0.08838834764831845f;   // 1/sqrt(128)

    for (int kt = 0; kt <= qt; ++kt) {
        __syncthreads();   // prior PV reads done before K/V overwrite (also covers Q load)
        // load K (transposed) and V (direct)
        for (int i = t; i < 64 * 32; i += 256) {
            int r  = i >> 5;
            int c4 = i & 31;
            const float* kp = base + DIN + (size_t)(kt * 64 + r) * QKVN + c4 * 4;
            float4 kv = *(const float4*)kp;
            Ks[(c4 * 4 + 0) * 64 + r] = kv.x;
            Ks[(c4 * 4 + 1) * 64 + r] = kv.y;
            Ks[(c4 * 4 + 2) * 64 + r] = kv.z;
            Ks[(c4 * 4 + 3) * 64 + r] = kv.w;
            float4 vv = *(const float4*)(kp + DIN);
            *(float4*)(&Vs[r * 128 + c4 * 4]) = vv;
        }
        __syncthreads();

        // S = Q K^T  (each thread: 4q x 4k)
        float s[4][4];
        #pragma unroll
        for (int qi = 0; qi < 4; ++qi)
            #pragma unroll
            for (int kj = 0; kj < 4; ++kj) s[qi][kj] = 0.f;

        #pragma unroll 4
        for (int d = 0; d < 128; ++d) {
            float qv[4], kv[4];
            *(float4*)qv = *(float4*)(&Qs[d * 64 + ty * 4]);
            *(float4*)kv = *(float4*)(&Ks[d * 64 + tx * 4]);
            #pragma unroll
            for (int qi = 0; qi < 4; ++qi)
                #pragma unroll
                for (int kj = 0; kj < 4; ++kj)
                    s[qi][kj] = fmaf(qv[qi], kv[kj], s[qi][kj]);
        }

        // scale + causal mask
        #pragma unroll
        for (int qi = 0; qi < 4; ++qi)
            #pragma unroll
            for (int kj = 0; kj < 4; ++kj) {
                float v = s[qi][kj] * scale;
                if (kt == qt && (tx * 4 + kj) > (ty * 4 + qi)) v = -INFINITY;
                s[qi][kj] = v;
            }

        // online softmax
        #pragma unroll
        for (int qi = 0; qi < 4; ++qi) {
            float rm = fmaxf(fmaxf(s[qi][0], s[qi][1]), fmaxf(s[qi][2], s[qi][3]));
            #pragma unroll
            for (int w = 1; w < 16; w <<= 1)
                rm = fmaxf(rm, __shfl_xor_sync(0xffffffffu, rm, w));
            float mn   = fmaxf(m[qi], rm);
            float corr = expf(m[qi] - mn);
            float rs = 0.f;
            #pragma unroll
            for (int kj = 0; kj < 4; ++kj) {
                float p = expf(s[qi][kj] - mn);
                s[qi][kj] = p;
                rs += p;
            }
            #pragma unroll
            for (int w = 1; w < 16; w <<= 1)
                rs += __shfl_xor_sync(0xffffffffu, rs, w);
            l[qi] = l[qi] * corr + rs;
            m[qi] = mn;
            #pragma unroll
            for (int dj = 0; dj < 8; ++dj) o[qi][dj] *= corr;
        }

        // write P transposed: Ps[k][q]
        #pragma unroll
        for (int kj = 0; kj < 4; ++kj)
            *(float4*)(&Ps[(tx * 4 + kj) * 68 + ty * 4]) =
                make_float4(s[0][kj], s[1][kj], s[2][kj], s[3][kj]);
        __syncthreads();

        // O += P V   (each thread: 4q x 8d, d0 = tx*8)
        #pragma unroll 4
        for (int kk = 0; kk < 64; ++kk) {
            float pv[4], vv[8];
            *(float4*)pv       = *(float4*)(&Ps[kk * 68 + ty * 4]);
            *(float4*)vv       = *(float4*)(&Vs[kk * 128 + tx * 8]);
            *(float4*)(vv + 4) = *(float4*)(&Vs[kk * 128 + tx * 8 + 4]);
            #pragma unroll
            for (int qi = 0; qi < 4; ++qi)
                #pragma unroll
                for (int dj = 0; dj < 8; ++dj)
                    o[qi][dj] = fmaf(pv[qi], vv[dj], o[qi][dj]);
        }
    }

    // epilogue: normalize and write
    #pragma unroll
    for (int qi = 0; qi < 4; ++qi) {
        float inv = 1.f / l[qi];
        size_t row = (size_t)b * SEQ + qt * 64 + ty * 4 + qi;
        float* op = out + row * DIN + h * HDIM + tx * 8;
        *(float4*)(op)     = make_float4(o[qi][0] * inv, o[qi][1] * inv, o[qi][2] * inv, o[qi][3] * inv);
        *(float4*)(op + 4) = make_float4(o[qi][4] * inv, o[qi][5] * inv, o[qi][6] * inv, o[qi][7] * inv);
    }
}

// ---------------- launch ----------------
extern "C" void kernel_launch(void* const* d_in, const int* in_sizes, int n_in,
                              void* d_out, int out_size)
{
    const float* x     = (const float*)d_in[0];   // [2,2048,2048]
    const float* Wqkv  = (const float*)d_in[1];   // [2048,6144]
    const float* Wproj = (const float*)d_in[2];   // [2048,2048]
    float* out = (float*)d_out;                    // [2,2048,2048]

    float *qkv_ptr, *att_ptr;
    cudaGetSymbolAddress((void**)&qkv_ptr, g_qkv);
    cudaGetSymbolAddress((void**)&att_ptr, g_att);

    // rope tables
    freq_kernel<<<(SEQ * HPAIR + 255) / 256, 256>>>();

    // qkv = x @ Wqkv : [4096,2048]x[2048,6144]
    {
        dim3 grid(QKVN / 128, MROWS / 128);
        sgemm128<<<grid, 256>>>(x, Wqkv, qkv_ptr, MROWS, QKVN, DIN);
    }

    // rope on q,k
    {
        int total = BATCH * SEQ * NHEAD * HPAIR;
        rope_kernel<<<(total + 255) / 256, 256>>>(qkv_ptr);
    }

    // attention
    {
        int smem_bytes = (128 * 64 + 128 * 64 + 64 * 128 + 64 * 68) * sizeof(float);
        cudaFuncSetAttribute(attn_kernel, cudaFuncAttributeMaxDynamicSharedMemorySize, smem_bytes);
        dim3 grid(SEQ / 64, NHEAD, BATCH);
        attn_kernel<<<grid, 256, smem_bytes>>>(qkv_ptr, att_ptr);
    }

    // out = att @ Wproj : [4096,2048]x[2048,2048]
    {
        dim3 grid(DIN / 128, MROWS / 128);
        sgemm128<<<grid, 256>>>(att_ptr, Wproj, out, MROWS, DIN, DIN);
    }
}